// round 13
// baseline (speedup 1.0000x reference)
#include <cuda_runtime.h>
#include <math.h>
#include <float.h>

#define Bb 2
#define Nn 2048
#define Cc 128
#define Kk 16
#define EPSf 1e-6f
#define BNEPSf 1e-5f
#define BN_TOT (Bb*Nn)          // 4096
#define BNK (Bb*Nn*Kk)          // 65536
#define CH_MAIN 272
#define CO_MAIN 256
#define CH_NBR 132
#define CO_NBR 128
#define STATS_G 256

// ---------------- scratch (device globals; no allocation allowed) ----------
__device__ float g_inner[(size_t)Bb*Nn*Nn];   // [b][src q][dst p]
__device__ float g_buf1[(size_t)BNK*CO_MAIN];
__device__ float g_buf2[(size_t)BNK*CO_MAIN];
__device__ float g_descT_src[(size_t)BN_TOT*Cc];
__device__ float g_descT_dst[(size_t)BN_TOT*Cc];
__device__ float g_nbrT_src[(size_t)BN_TOT*Cc];   // [b][c][n]
__device__ float g_nbrT_dst[(size_t)BN_TOT*Cc];
__device__ float g_norm_src[BN_TOT], g_norm_dst[BN_TOT];
__device__ float g_n2_dst[BN_TOT];
__device__ float g_nbrnorm_src[BN_TOT], g_nbrnorm_dst[BN_TOT];
__device__ int   g_idx[BNK];
__device__ int   g_sidx[BNK];
__device__ float g_maxq[BN_TOT];   // per-src max (over dst)
__device__ float g_maxp[BN_TOT];   // per-dst max (over src)
__device__ float g_sims[(size_t)4*BNK];
__device__ float g_att[(size_t)BN_TOT*CO_MAIN];   // also reused as Pn
__device__ float g_h1[(size_t)BN_TOT*CO_MAIN];    // also reused as Ps
__device__ float g_h2[(size_t)BN_TOT*CO_MAIN];    // also reused as Pd
__device__ float g_psum[STATS_G*CO_MAIN];
__device__ float g_psq[STATS_G*CO_MAIN];
__device__ float g_scale[CO_MAIN], g_shift[CO_MAIN];
// packed layer-1 weight blocks
__device__ float g_W0s[CO_MAIN*Cc];     // c1_W0[:,10:138]
__device__ float g_W0d[CO_MAIN*Cc];     // c1_W0[:,138:266]
__device__ float g_W0r[CO_MAIN*16];     // c1_W0[:,{0..9,266..271}]
__device__ float g_W0nd[CO_NBR*Cc];     // c2_W0[:,0:128]
__device__ float g_W0ng[CO_NBR*4];      // c2_W0[:,128:132]

// ---------------- weight pack kernels --------------------------------------
__global__ void pack_kernel(const float* __restrict__ in, float* __restrict__ out,
                            int n, int kout, int stride, int off) {
    int i = blockIdx.x * blockDim.x + threadIdx.x;
    if (i >= n * kout) return;
    int r = i / kout, k = i % kout;
    out[i] = in[(size_t)r * stride + off + k];
}

__global__ void pack_w0r_kernel(const float* __restrict__ in) {
    int i = blockIdx.x * blockDim.x + threadIdx.x;
    if (i >= CO_MAIN * 16) return;
    int r = i >> 4, k = i & 15;
    int col = (k < 10) ? k : (k + 256);   // {0..9, 266..271}
    g_W0r[i] = in[(size_t)r * CH_MAIN + col];
}

// ---------------- transpose [B,C,N] -> [B,N,C] -----------------------------
__global__ void transpose_kernel(const float* __restrict__ in, float* __restrict__ out) {
    __shared__ float t[32][33];
    int b = blockIdx.z;
    int n0 = blockIdx.x * 32, c0 = blockIdx.y * 32;
    int x = threadIdx.x, y = threadIdx.y;
#pragma unroll
    for (int i = 0; i < 32; i += 8)
        t[y + i][x] = in[(size_t)b*Cc*Nn + (size_t)(c0 + y + i)*Nn + n0 + x];
    __syncthreads();
#pragma unroll
    for (int i = 0; i < 32; i += 8)
        out[(size_t)b*Nn*Cc + (size_t)(n0 + y + i)*Cc + c0 + x] = t[x][y + i];
}

// ---------------- per-point descriptor norms -------------------------------
__global__ void norms_kernel(const float* __restrict__ descT, float* __restrict__ nrm,
                             float* __restrict__ n2) {
    __shared__ float red[128];
    int bn = blockIdx.x; int c = threadIdx.x;
    float v = descT[(size_t)bn*Cc + c];
    red[c] = v * v; __syncthreads();
    for (int off = 64; off > 0; off >>= 1) {
        if (c < off) red[c] += red[c + off];
        __syncthreads();
    }
    if (c == 0) { float s = red[0]; if (n2) n2[bn] = s; nrm[bn] = sqrtf(s); }
}

// ---------------- fused BN+ReLU on a float4 of A ---------------------------
__device__ __forceinline__ float4 apply4(float4 a, int k) {
    float4 sc = *(const float4*)&g_scale[k];
    float4 sh = *(const float4*)&g_shift[k];
    a.x = fmaxf(fmaf(a.x, sc.x, sh.x), 0.f);
    a.y = fmaxf(fmaf(a.y, sc.y, sh.y), 0.f);
    a.z = fmaxf(fmaf(a.z, sc.z, sh.z), 0.f);
    a.w = fmaxf(fmaf(a.w, sc.w, sh.w), 0.f);
    return a;
}

// ---------------- NT gemm 128x128x8, 8x8/thread, double-buffered -----------
// C[m][n] = sum_k A[m][k] * W[n][k].  Kc must be a multiple of 8.
// fuse!=0: A := relu(A*g_scale[k] + g_shift[k]) on load.
__global__ void gemm_nt128_kernel(const float* __restrict__ A, const float* __restrict__ W,
                                  float* __restrict__ Cm, int M, int Nc, int Kc, int fuse) {
    __shared__ float As[2][8][128];
    __shared__ float Bs[2][8][128];
    int m0 = blockIdx.y * 128, n0 = blockIdx.x * 128;
    int tid = threadIdx.x;
    int lr = tid >> 1;            // 0..127
    int lk = (tid & 1) * 4;       // 0 or 4
    int ty = tid >> 4, tx = tid & 15;
    const float* Arow = A + (size_t)(m0 + lr) * Kc + lk;
    const float* Wrow = W + (size_t)(n0 + lr) * Kc + lk;
    float acc[8][8];
#pragma unroll
    for (int i = 0; i < 8; i++)
#pragma unroll
        for (int j = 0; j < 8; j++) acc[i][j] = 0.f;

    float4 av = *(const float4*)Arow;
    float4 bv = *(const float4*)Wrow;
    if (fuse) av = apply4(av, lk);
    As[0][lk+0][lr] = av.x; As[0][lk+1][lr] = av.y;
    As[0][lk+2][lr] = av.z; As[0][lk+3][lr] = av.w;
    Bs[0][lk+0][lr] = bv.x; Bs[0][lk+1][lr] = bv.y;
    Bs[0][lk+2][lr] = bv.z; Bs[0][lk+3][lr] = bv.w;
    __syncthreads();
    int nb = 0;
    for (int kt = 0; kt < Kc; kt += 8) {
        bool nxt = (kt + 8) < Kc;
        float4 a2, b2;
        if (nxt) {
            a2 = *(const float4*)(Arow + kt + 8);
            b2 = *(const float4*)(Wrow + kt + 8);
            if (fuse) a2 = apply4(a2, kt + 8 + lk);
        }
#pragma unroll
        for (int kkk = 0; kkk < 8; kkk++) {
            float a[8], b[8];
            *(float4*)&a[0] = *(const float4*)&As[nb][kkk][ty * 4];
            *(float4*)&a[4] = *(const float4*)&As[nb][kkk][64 + ty * 4];
            *(float4*)&b[0] = *(const float4*)&Bs[nb][kkk][tx * 4];
            *(float4*)&b[4] = *(const float4*)&Bs[nb][kkk][64 + tx * 4];
#pragma unroll
            for (int i = 0; i < 8; i++)
#pragma unroll
                for (int j = 0; j < 8; j++) acc[i][j] = fmaf(a[i], b[j], acc[i][j]);
        }
        if (nxt) {
            int nb2 = nb ^ 1;
            As[nb2][lk+0][lr] = a2.x; As[nb2][lk+1][lr] = a2.y;
            As[nb2][lk+2][lr] = a2.z; As[nb2][lk+3][lr] = a2.w;
            Bs[nb2][lk+0][lr] = b2.x; Bs[nb2][lk+1][lr] = b2.y;
            Bs[nb2][lk+2][lr] = b2.z; Bs[nb2][lk+3][lr] = b2.w;
            nb = nb2;
        }
        __syncthreads();
    }
#pragma unroll
    for (int i = 0; i < 8; i++) {
        int row = m0 + ((i < 4) ? (ty * 4 + i) : (64 + ty * 4 + i - 4));
        *(float4*)&Cm[(size_t)row * Nc + n0 + tx * 4] =
            make_float4(acc[i][0], acc[i][1], acc[i][2], acc[i][3]);
        *(float4*)&Cm[(size_t)row * Nc + n0 + 64 + tx * 4] =
            make_float4(acc[i][4], acc[i][5], acc[i][6], acc[i][7]);
    }
}

// ---------------- TN gemm 128x128x8 (batched over Bb) ----------------------
// C[b][m][n] = sum_k A[b][k][m]*B[b][k][n];  A,B pitch Nn.
__global__ void gemm_tn128_kernel(const float* __restrict__ A, const float* __restrict__ Bm,
                                  float* __restrict__ Cm, int Kc) {
    __shared__ float As[2][8][128];
    __shared__ float Bs[2][8][128];
    int b = blockIdx.z;
    const float* Ab = A + (size_t)b * Kc * Nn;
    const float* Bp = Bm + (size_t)b * Kc * Nn;
    float* Cb = Cm + (size_t)b * Nn * Nn;
    int m0 = blockIdx.y * 128, n0 = blockIdx.x * 128;
    int tid = threadIdx.x;
    int lk2 = tid >> 5;
    int lm = (tid & 31) * 4;
    int ty = tid >> 4, tx = tid & 15;
    float acc[8][8];
#pragma unroll
    for (int i = 0; i < 8; i++)
#pragma unroll
        for (int j = 0; j < 8; j++) acc[i][j] = 0.f;

    *(float4*)&As[0][lk2][lm] = *(const float4*)&Ab[(size_t)lk2 * Nn + m0 + lm];
    *(float4*)&Bs[0][lk2][lm] = *(const float4*)&Bp[(size_t)lk2 * Nn + n0 + lm];
    __syncthreads();
    int nb = 0;
    for (int kt = 0; kt < Kc; kt += 8) {
        bool nxt = (kt + 8) < Kc;
        float4 a2, b2;
        if (nxt) {
            a2 = *(const float4*)&Ab[(size_t)(kt + 8 + lk2) * Nn + m0 + lm];
            b2 = *(const float4*)&Bp[(size_t)(kt + 8 + lk2) * Nn + n0 + lm];
        }
#pragma unroll
        for (int kkk = 0; kkk < 8; kkk++) {
            float a[8], b[8];
            *(float4*)&a[0] = *(const float4*)&As[nb][kkk][ty * 4];
            *(float4*)&a[4] = *(const float4*)&As[nb][kkk][64 + ty * 4];
            *(float4*)&b[0] = *(const float4*)&Bs[nb][kkk][tx * 4];
            *(float4*)&b[4] = *(const float4*)&Bs[nb][kkk][64 + tx * 4];
#pragma unroll
            for (int i = 0; i < 8; i++)
#pragma unroll
                for (int j = 0; j < 8; j++) acc[i][j] = fmaf(a[i], b[j], acc[i][j]);
        }
        if (nxt) {
            int nb2 = nb ^ 1;
            *(float4*)&As[nb2][lk2][lm] = a2;
            *(float4*)&Bs[nb2][lk2][lm] = b2;
            nb = nb2;
        }
        __syncthreads();
    }
#pragma unroll
    for (int i = 0; i < 8; i++) {
        int row = m0 + ((i < 4) ? (ty * 4 + i) : (64 + ty * 4 + i - 4));
        *(float4*)&Cb[(size_t)row * Nn + n0 + tx * 4] =
            make_float4(acc[i][0], acc[i][1], acc[i][2], acc[i][3]);
        *(float4*)&Cb[(size_t)row * Nn + n0 + 64 + tx * 4] =
            make_float4(acc[i][4], acc[i][5], acc[i][6], acc[i][7]);
    }
}

// ---------------- layer-1 combine kernels ----------------------------------
__global__ void main_l1_combine_kernel(const float* __restrict__ sxyz,
                                       const float* __restrict__ dxyz,
                                       const float* __restrict__ sw,
                                       const float* __restrict__ dw,
                                       const float* __restrict__ Ps,
                                       const float* __restrict__ Pd,
                                       float* __restrict__ Y) {
    __shared__ float rest[16];
    int t = blockIdx.x;
    int bn = t >> 4; int b = bn >> 11;
    int i = g_idx[t]; int gi = b*Nn + i;
    int o = threadIdx.x;
    if (o == 0) {
        float sx = sxyz[bn*3+0], sy = sxyz[bn*3+1], sz = sxyz[bn*3+2];
        float kx = dxyz[gi*3+0], ky = dxyz[gi*3+1], kz = dxyz[gi*3+2];
        float dx = kx - sx, dy = ky - sy, dz = kz - sz;
        rest[0] = dx; rest[1] = dy; rest[2] = dz;
        rest[3] = sqrtf(dx*dx + dy*dy + dz*dz);
        rest[4] = sx; rest[5] = sy; rest[6] = sz;
        rest[7] = kx; rest[8] = ky; rest[9] = kz;
        rest[10] = sw[bn]; rest[11] = dw[gi];
        rest[12] = g_sims[0*(size_t)BNK + t];
        rest[13] = g_sims[1*(size_t)BNK + t];
        rest[14] = g_sims[2*(size_t)BNK + t];
        rest[15] = g_sims[3*(size_t)BNK + t];
    }
    __syncthreads();
    float acc = Ps[(size_t)bn*CO_MAIN + o] + Pd[(size_t)gi*CO_MAIN + o];
    const float4* w = (const float4*)&g_W0r[o * 16];
#pragma unroll
    for (int r = 0; r < 4; r++) {
        float4 wv = w[r];
        acc += wv.x*rest[r*4+0] + wv.y*rest[r*4+1] + wv.z*rest[r*4+2] + wv.w*rest[r*4+3];
    }
    Y[(size_t)t*CO_MAIN + o] = acc;
}

__global__ void nbr_l1_combine_kernel(const float* __restrict__ xyz,
                                      const float* __restrict__ Pn,
                                      float* __restrict__ Y) {
    __shared__ float rest[4];
    int t = blockIdx.x;
    int bn = t >> 4; int b = bn >> 11;
    int i = g_sidx[t]; int gi = b*Nn + i;
    int o = threadIdx.x;
    if (o == 0) {
        float dx = xyz[gi*3+0] - xyz[bn*3+0];
        float dy = xyz[gi*3+1] - xyz[bn*3+1];
        float dz = xyz[gi*3+2] - xyz[bn*3+2];
        rest[0] = dx; rest[1] = dy; rest[2] = dz;
        rest[3] = sqrtf(dx*dx + dy*dy + dz*dz);
    }
    __syncthreads();
    float4 wv = *(const float4*)&g_W0ng[o * 4];
    float acc = Pn[(size_t)gi*CO_NBR + o]
              + wv.x*rest[0] + wv.y*rest[1] + wv.z*rest[2] + wv.w*rest[3];
    Y[(size_t)t*CO_NBR + o] = acc;
}

// ---------------- BatchNorm stats (deterministic two-stage) ----------------
__global__ void bn_stats1_kernel(const float* __restrict__ Y, int M, int Cout) {
    int c = threadIdx.x;
    float s = 0.f, s2 = 0.f;
    for (int r = blockIdx.x; r < M; r += STATS_G) {
        float v = Y[(size_t)r*Cout + c];
        s += v; s2 += v * v;
    }
    g_psum[blockIdx.x*Cout + c] = s;
    g_psq[blockIdx.x*Cout + c]  = s2;
}

__global__ void bn_stats2_kernel(int M, int Cout, const float* __restrict__ gamma,
                                 const float* __restrict__ beta) {
    int c = threadIdx.x;
    float s = 0.f, s2 = 0.f;
    for (int g = 0; g < STATS_G; g++) { s += g_psum[g*Cout + c]; s2 += g_psq[g*Cout + c]; }
    float inv = 1.f / (float)M;
    float mu = s * inv;
    float var = fmaxf(s2 * inv - mu * mu, 0.f);
    float sc = gamma[c] * rsqrtf(var + BNEPSf);
    g_scale[c] = sc;
    g_shift[c] = beta[c] - mu * sc;
}

__global__ void bn_apply_relu_kernel(float* __restrict__ Y, int total, int cmask) {
    int i = blockIdx.x * blockDim.x + threadIdx.x;
    if (i >= total) return;
    int c = i & cmask;
    Y[i] = fmaxf(Y[i] * g_scale[c] + g_shift[c], 0.f);
}

// ---------------- KNN (descriptor space): row-coalesced --------------------
__global__ void knn_desc_kernel() {
    __shared__ float key[Nn];
    __shared__ float rv[256]; __shared__ int ri[256];
    int bj = blockIdx.x;
    const float* row = g_inner + (size_t)bj*Nn;   // inner[b][src j][*]
    int b = bj >> 11;
    for (int i = threadIdx.x; i < Nn; i += 256)
        key[i] = g_n2_dst[b*Nn + i] - 2.f * row[i];
    __syncthreads();
    for (int s = 0; s < Kk; s++) {
        float bvv = FLT_MAX; int bii = Nn;
        for (int i = threadIdx.x; i < Nn; i += 256) {
            float v = key[i];
            if (v < bvv) { bvv = v; bii = i; }
        }
        rv[threadIdx.x] = bvv; ri[threadIdx.x] = bii;
        __syncthreads();
        for (int off = 128; off > 0; off >>= 1) {
            if (threadIdx.x < off) {
                float v2 = rv[threadIdx.x + off]; int i2 = ri[threadIdx.x + off];
                if (v2 < rv[threadIdx.x] ||
                    (v2 == rv[threadIdx.x] && i2 < ri[threadIdx.x])) {
                    rv[threadIdx.x] = v2; ri[threadIdx.x] = i2;
                }
            }
            __syncthreads();
        }
        if (threadIdx.x == 0) { g_idx[bj*Kk + s] = ri[0]; key[ri[0]] = FLT_MAX; }
        __syncthreads();
    }
}

// ---------------- KNN (spatial, self) --------------------------------------
__global__ void knn_spatial_kernel(const float* __restrict__ xyz, int* __restrict__ oidx) {
    __shared__ float key[Nn];
    __shared__ float rv[256]; __shared__ int ri[256];
    int bj = blockIdx.x; int b = bj >> 11;
    float qx = xyz[(size_t)bj*3 + 0], qy = xyz[(size_t)bj*3 + 1], qz = xyz[(size_t)bj*3 + 2];
    const float* xb = xyz + (size_t)b*Nn*3;
    for (int i = threadIdx.x; i < Nn; i += 256) {
        float dx = xb[i*3 + 0] - qx, dy = xb[i*3 + 1] - qy, dz = xb[i*3 + 2] - qz;
        key[i] = dx*dx + dy*dy + dz*dz;
    }
    __syncthreads();
    for (int s = 0; s < Kk; s++) {
        float bvv = FLT_MAX; int bii = Nn;
        for (int i = threadIdx.x; i < Nn; i += 256) {
            float v = key[i];
            if (v < bvv) { bvv = v; bii = i; }
        }
        rv[threadIdx.x] = bvv; ri[threadIdx.x] = bii;
        __syncthreads();
        for (int off = 128; off > 0; off >>= 1) {
            if (threadIdx.x < off) {
                float v2 = rv[threadIdx.x + off]; int i2 = ri[threadIdx.x + off];
                if (v2 < rv[threadIdx.x] ||
                    (v2 == rv[threadIdx.x] && i2 < ri[threadIdx.x])) {
                    rv[threadIdx.x] = v2; ri[threadIdx.x] = i2;
                }
            }
            __syncthreads();
        }
        if (threadIdx.x == 0) { oidx[bj*Kk + s] = ri[0]; key[ri[0]] = FLT_MAX; }
        __syncthreads();
    }
}

// ---------------- cosine maxima over inner[b][q][p] ------------------------
// maxq[q] = max_p inner[q][p]/(nq[q]*np[p]+eps)   (row scan)
__global__ void rowmax_kernel(const float* __restrict__ nq, const float* __restrict__ np) {
    __shared__ float red[256];
    int bq = blockIdx.x; int b = bq >> 11;
    const float* row = g_inner + (size_t)bq*Nn;
    float nqv = nq[bq];
    const float* npb = np + b*Nn;
    float m = -FLT_MAX;
    for (int p = threadIdx.x; p < Nn; p += 256)
        m = fmaxf(m, row[p] / (nqv * npb[p] + EPSf));
    red[threadIdx.x] = m; __syncthreads();
    for (int off = 128; off > 0; off >>= 1) {
        if (threadIdx.x < off) red[threadIdx.x] = fmaxf(red[threadIdx.x], red[threadIdx.x + off]);
        __syncthreads();
    }
    if (threadIdx.x == 0) g_maxq[bq] = red[0];
}

// maxp[p] = max_q inner[q][p]/(nq[q]*np[p]+eps)   (column scan, p across tid.x)
__global__ void colmax_kernel(const float* __restrict__ nq, const float* __restrict__ np) {
    __shared__ float sm[8][32];
    int b = blockIdx.y;
    int p = blockIdx.x * 32 + threadIdx.x;
    float npv = np[b*Nn + p];
    const float* colb = g_inner + (size_t)b*Nn*Nn + p;
    const float* nqb = nq + b*Nn;
    float m = -FLT_MAX;
    for (int q = threadIdx.y; q < Nn; q += 8)
        m = fmaxf(m, colb[(size_t)q*Nn] / (nqb[q] * npv + EPSf));
    sm[threadIdx.y][threadIdx.x] = m; __syncthreads();
    if (threadIdx.y == 0) {
#pragma unroll
        for (int r = 1; r < 8; r++) m = fmaxf(m, sm[r][threadIdx.x]);
        g_maxp[b*Nn + p] = m;
    }
}

__global__ void gather_sims_kernel(const float* __restrict__ nd, const float* __restrict__ ns,
                                   float* __restrict__ s1, float* __restrict__ s2) {
    int t = blockIdx.x * blockDim.x + threadIdx.x;
    if (t >= BNK) return;
    int bn = t >> 4; int b = bn >> 11;
    int i = g_idx[t];
    float innv = g_inner[(size_t)bn*Nn + i];            // inner[src bn][dst i]
    float cosv = innv / (nd[b*Nn + i] * ns[bn] + EPSf);
    s1[t] = cosv / (g_maxq[bn] + EPSf);                 // src_dst: /max over dst for src
    s2[t] = cosv / (g_maxp[b*Nn + i] + EPSf);           // dst_src: /max over src for dst
}

// ---------------- neighbor-branch finalize (reads activated buf1) ----------
__global__ void nbr_finalize_kernel(const float* __restrict__ descT, float* __restrict__ nbrT,
                                    float* __restrict__ nnorm) {
    __shared__ float red[128]; __shared__ float wk[Kk];
    int bn = blockIdx.x; int b = bn >> 11; int n = bn & (Nn - 1);
    int c = threadIdx.x;
    for (int k = 0; k < Kk; k++) {
        red[c] = g_buf1[((size_t)bn*Kk + k)*CO_NBR + c];
        __syncthreads();
        for (int off = 64; off > 0; off >>= 1) {
            if (c < off) red[c] = fmaxf(red[c], red[c + off]);
            __syncthreads();
        }
        if (c == 0) wk[k] = red[0];
        __syncthreads();
    }
    if (c == 0) {
        float mx = -FLT_MAX;
        for (int k = 0; k < Kk; k++) mx = fmaxf(mx, wk[k]);
        float s = 0.f;
        for (int k = 0; k < Kk; k++) { wk[k] = expf(wk[k] - mx); s += wk[k]; }
        float is = 1.f / s;
        for (int k = 0; k < Kk; k++) wk[k] *= is;
    }
    __syncthreads();
    float acc = 0.f;
    for (int k = 0; k < Kk; k++) {
        int i = g_sidx[bn*Kk + k];
        acc += wk[k] * descT[(size_t)(b*Nn + i)*Cc + c];
    }
    nbrT[(size_t)b*Cc*Nn + (size_t)c*Nn + n] = acc;
    red[c] = acc * acc; __syncthreads();
    for (int off = 64; off > 0; off >>= 1) {
        if (c < off) red[c] += red[c + off];
        __syncthreads();
    }
    if (c == 0) nnorm[bn] = sqrtf(red[0]);
}

// ---------------- attention pooling (reads activated buf1) -----------------
__global__ void att_finalize_kernel(const float* __restrict__ dxyz, float* __restrict__ out_corres) {
    __shared__ float red[256]; __shared__ float wk[Kk];
    int bn = blockIdx.x; int b = bn >> 11;
    int c = threadIdx.x;
    for (int k = 0; k < Kk; k++) {
        red[c] = g_buf1[((size_t)bn*Kk + k)*CO_MAIN + c];
        __syncthreads();
        for (int off = 128; off > 0; off >>= 1) {
            if (c < off) red[c] = fmaxf(red[c], red[c + off]);
            __syncthreads();
        }
        if (c == 0) wk[k] = red[0];
        __syncthreads();
    }
    if (c == 0) {
        float mx = -FLT_MAX;
        for (int k = 0; k < Kk; k++) mx = fmaxf(mx, wk[k]);
        float s = 0.f;
        for (int k = 0; k < Kk; k++) { wk[k] = expf(wk[k] - mx); s += wk[k]; }
        float is = 1.f / s;
        for (int k = 0; k < Kk; k++) wk[k] *= is;
    }
    __syncthreads();
    float acc = 0.f;
    for (int k = 0; k < Kk; k++)
        acc += wk[k] * g_buf1[((size_t)bn*Kk + k)*CO_MAIN + c];
    g_att[(size_t)bn*CO_MAIN + c] = acc;
    if (c < 3) {
        float s = 0.f;
        for (int k = 0; k < Kk; k++) {
            int i = g_idx[bn*Kk + k];
            s += wk[k] * dxyz[(b*Nn + i)*3 + c];
        }
        out_corres[bn*3 + c] = s;
    }
}

// ---------------- final sigmoid head ---------------------------------------
__global__ void mlp3_kernel(const float* __restrict__ W, const float* __restrict__ bias,
                            float* __restrict__ out) {
    __shared__ float red[256];
    int bn = blockIdx.x; int c = threadIdx.x;
    red[c] = g_h2[(size_t)bn*CO_MAIN + c] * W[c];
    __syncthreads();
    for (int off = 128; off > 0; off >>= 1) {
        if (c < off) red[c] += red[c + off];
        __syncthreads();
    }
    if (c == 0) {
        float z = red[0] + bias[0];
        out[bn] = 1.f / (1.f + expf(-z));
    }
}

// ---------------- host-side helpers ----------------------------------------
static void bn_stats(const float* Y, int M, int Cout, const float* gamma, const float* beta) {
    bn_stats1_kernel<<<STATS_G, Cout>>>(Y, M, Cout);
    bn_stats2_kernel<<<1, Cout>>>(M, Cout, gamma, beta);
}

static void bn_apply(float* Y, int M, int Cout) {
    int total = M * Cout;
    bn_apply_relu_kernel<<<(total + 255) / 256, 256>>>(Y, total, Cout - 1);
}

// gemm (with optional fused BN-on-A-read) then stats of the new output
static void conv_stats(const float* X, const float* W, float* Y, int M, int Cout, int Cin,
                       int fuse, const float* gamma, const float* beta) {
    gemm_nt128_kernel<<<dim3(Cout / 128, M / 128), 256>>>(X, W, Y, M, Cout, Cin, fuse);
    bn_stats(Y, M, Cout, gamma, beta);
}

extern "C" void kernel_launch(void* const* d_in, const int* in_sizes, int n_in,
                              void* d_out, int out_size) {
    const float* src_xyz  = (const float*)d_in[0];
    const float* src_desc = (const float*)d_in[1];
    const float* dst_xyz  = (const float*)d_in[2];
    const float* dst_desc = (const float*)d_in[3];
    const float* src_w    = (const float*)d_in[4];
    const float* dst_w    = (const float*)d_in[5];
    const float* c1_W0 = (const float*)d_in[6];
    const float* c1_W  = (const float*)d_in[7];
    const float* c1_g  = (const float*)d_in[8];
    const float* c1_b  = (const float*)d_in[9];
    const float* c2_W0 = (const float*)d_in[10];
    const float* c2_W  = (const float*)d_in[11];
    const float* c2_g  = (const float*)d_in[12];
    const float* c2_b  = (const float*)d_in[13];
    const float* m1_W  = (const float*)d_in[14];
    // d_in[15] m1_bias: cancels exactly under train-mode BN
    const float* m1_g  = (const float*)d_in[16];
    const float* m1_b  = (const float*)d_in[17];
    const float* m2_W  = (const float*)d_in[18];
    // d_in[19] m2_bias: cancels under BN
    const float* m2_g  = (const float*)d_in[20];
    const float* m2_b  = (const float*)d_in[21];
    const float* m3_W  = (const float*)d_in[22];
    const float* m3_bias = (const float*)d_in[23];
    float* outp = (float*)d_out;

    float *inner, *buf1, *buf2, *dTs, *dTd, *nTs, *nTd;
    float *nsrc, *ndst, *n2d, *nnsrc, *nndst, *sims, *att, *h1, *h2;
    float *W0s, *W0d, *W0nd, *W0ng;
    int *sidxp;
    cudaGetSymbolAddress((void**)&inner, g_inner);
    cudaGetSymbolAddress((void**)&buf1,  g_buf1);
    cudaGetSymbolAddress((void**)&buf2,  g_buf2);
    cudaGetSymbolAddress((void**)&dTs,   g_descT_src);
    cudaGetSymbolAddress((void**)&dTd,   g_descT_dst);
    cudaGetSymbolAddress((void**)&nTs,   g_nbrT_src);
    cudaGetSymbolAddress((void**)&nTd,   g_nbrT_dst);
    cudaGetSymbolAddress((void**)&nsrc,  g_norm_src);
    cudaGetSymbolAddress((void**)&ndst,  g_norm_dst);
    cudaGetSymbolAddress((void**)&n2d,   g_n2_dst);
    cudaGetSymbolAddress((void**)&nnsrc, g_nbrnorm_src);
    cudaGetSymbolAddress((void**)&nndst, g_nbrnorm_dst);
    cudaGetSymbolAddress((void**)&sims,  g_sims);
    cudaGetSymbolAddress((void**)&att,   g_att);
    cudaGetSymbolAddress((void**)&h1,    g_h1);
    cudaGetSymbolAddress((void**)&h2,    g_h2);
    cudaGetSymbolAddress((void**)&W0s,   g_W0s);
    cudaGetSymbolAddress((void**)&W0d,   g_W0d);
    cudaGetSymbolAddress((void**)&W0nd,  g_W0nd);
    cudaGetSymbolAddress((void**)&W0ng,  g_W0ng);
    cudaGetSymbolAddress((void**)&sidxp, g_sidx);

    // Stage 0: transpose descriptors, norms, pack layer-1 weight blocks
    transpose_kernel<<<dim3(Nn/32, Cc/32, Bb), dim3(32, 8)>>>(src_desc, dTs);
    transpose_kernel<<<dim3(Nn/32, Cc/32, Bb), dim3(32, 8)>>>(dst_desc, dTd);
    norms_kernel<<<BN_TOT, 128>>>(dTs, nsrc, (float*)0);
    norms_kernel<<<BN_TOT, 128>>>(dTd, ndst, n2d);
    pack_kernel<<<(CO_MAIN*Cc + 255)/256, 256>>>(c1_W0, W0s, CO_MAIN, Cc, CH_MAIN, 10);
    pack_kernel<<<(CO_MAIN*Cc + 255)/256, 256>>>(c1_W0, W0d, CO_MAIN, Cc, CH_MAIN, 138);
    pack_w0r_kernel<<<(CO_MAIN*16 + 255)/256, 256>>>(c1_W0);
    pack_kernel<<<(CO_NBR*Cc + 255)/256, 256>>>(c2_W0, W0nd, CO_NBR, Cc, CH_NBR, 0);
    pack_kernel<<<(CO_NBR*4 + 255)/256, 256>>>(c2_W0, W0ng, CO_NBR, 4, CH_NBR, 128);

    // Stage 1: inner[b][src][dst], knn (row-coalesced), sims 0/1
    gemm_tn128_kernel<<<dim3(Nn/128, Nn/128, Bb), 256>>>(src_desc, dst_desc, inner, Cc);
    knn_desc_kernel<<<BN_TOT, 256>>>();
    rowmax_kernel<<<BN_TOT, 256>>>(nsrc, ndst);                 // maxq (per src)
    colmax_kernel<<<dim3(Nn/32, Bb), dim3(32, 8)>>>(nsrc, ndst);// maxp (per dst)
    gather_sims_kernel<<<BNK/256, 256>>>(ndst, nsrc, sims + 0*(size_t)BNK, sims + 1*(size_t)BNK);

    // Stage 2a: neighbor branch, src cloud
    knn_spatial_kernel<<<BN_TOT, 256>>>(src_xyz, sidxp);
    gemm_nt128_kernel<<<dim3(1, BN_TOT/128), 256>>>(dTs, W0nd, att /*Pn*/, BN_TOT, CO_NBR, Cc, 0);
    nbr_l1_combine_kernel<<<BNK, CO_NBR>>>(src_xyz, att, buf1);
    bn_stats(buf1, BNK, CO_NBR, c2_g + 0*Cc, c2_b + 0*Cc);
    conv_stats(buf1, c2_W + 0*Cc*Cc, buf2, BNK, CO_NBR, Cc, 1, c2_g + 1*Cc, c2_b + 1*Cc);
    conv_stats(buf2, c2_W + 1*Cc*Cc, buf1, BNK, CO_NBR, Cc, 1, c2_g + 2*Cc, c2_b + 2*Cc);
    bn_apply(buf1, BNK, CO_NBR);
    nbr_finalize_kernel<<<BN_TOT, 128>>>(dTs, nTs, nnsrc);

    // Stage 2b: neighbor branch, dst cloud
    knn_spatial_kernel<<<BN_TOT, 256>>>(dst_xyz, sidxp);
    gemm_nt128_kernel<<<dim3(1, BN_TOT/128), 256>>>(dTd, W0nd, att /*Pn*/, BN_TOT, CO_NBR, Cc, 0);
    nbr_l1_combine_kernel<<<BNK, CO_NBR>>>(dst_xyz, att, buf1);
    bn_stats(buf1, BNK, CO_NBR, c2_g + 0*Cc, c2_b + 0*Cc);
    conv_stats(buf1, c2_W + 0*Cc*Cc, buf2, BNK, CO_NBR, Cc, 1, c2_g + 1*Cc, c2_b + 1*Cc);
    conv_stats(buf2, c2_W + 1*Cc*Cc, buf1, BNK, CO_NBR, Cc, 1, c2_g + 2*Cc, c2_b + 2*Cc);
    bn_apply(buf1, BNK, CO_NBR);
    nbr_finalize_kernel<<<BN_TOT, 128>>>(dTd, nTd, nndst);

    // Stage 3: neighbor cosine sims 2/3 (inner[b][src][dst] again)
    gemm_tn128_kernel<<<dim3(Nn/128, Nn/128, Bb), 256>>>(nTs, nTd, inner, Cc);
    rowmax_kernel<<<BN_TOT, 256>>>(nnsrc, nndst);
    colmax_kernel<<<dim3(Nn/32, Bb), dim3(32, 8)>>>(nnsrc, nndst);
    gather_sims_kernel<<<BNK/256, 256>>>(nndst, nnsrc, sims + 2*(size_t)BNK, sims + 3*(size_t)BNK);

    // Stage 4: main branch
    gemm_nt128_kernel<<<dim3(CO_MAIN/128, BN_TOT/128), 256>>>(dTs, W0s, h1 /*Ps*/, BN_TOT, CO_MAIN, Cc, 0);
    gemm_nt128_kernel<<<dim3(CO_MAIN/128, BN_TOT/128), 256>>>(dTd, W0d, h2 /*Pd*/, BN_TOT, CO_MAIN, Cc, 0);
    main_l1_combine_kernel<<<BNK, CO_MAIN>>>(src_xyz, dst_xyz, src_w, dst_w, h1, h2, buf1);
    bn_stats(buf1, BNK, CO_MAIN, c1_g + 0*CO_MAIN, c1_b + 0*CO_MAIN);
    conv_stats(buf1, c1_W + 0*CO_MAIN*CO_MAIN, buf2, BNK, CO_MAIN, CO_MAIN, 1,
               c1_g + 1*CO_MAIN, c1_b + 1*CO_MAIN);
    conv_stats(buf2, c1_W + 1*CO_MAIN*CO_MAIN, buf1, BNK, CO_MAIN, CO_MAIN, 1,
               c1_g + 2*CO_MAIN, c1_b + 2*CO_MAIN);
    bn_apply(buf1, BNK, CO_MAIN);
    att_finalize_kernel<<<BN_TOT, 256>>>(dst_xyz, outp);

    // Stage 5: MLP head (m1/m2 biases cancel in BN)
    gemm_nt128_kernel<<<dim3(CO_MAIN/128, BN_TOT/128), 256>>>(att, m1_W, h1, BN_TOT, CO_MAIN, CO_MAIN, 0);
    bn_stats(h1, BN_TOT, CO_MAIN, m1_g, m1_b);
    conv_stats(h1, m2_W, h2, BN_TOT, CO_MAIN, CO_MAIN, 1, m2_g, m2_b);
    bn_apply(h2, BN_TOT, CO_MAIN);
    mlp3_kernel<<<BN_TOT, 256>>>(m3_W, m3_bias, outp + (size_t)BN_TOT*3);
}

// round 14
// speedup vs baseline: 1.0010x; 1.0010x over previous
#include <cuda_runtime.h>
#include <math.h>
#include <float.h>

#define Bb 2
#define Nn 2048
#define Cc 128
#define Kk 16
#define EPSf 1e-6f
#define BNEPSf 1e-5f
#define BN_TOT (Bb*Nn)          // 4096
#define BNK (Bb*Nn*Kk)          // 65536
#define CH_MAIN 272
#define CO_MAIN 256
#define CH_NBR 132
#define CO_NBR 128
#define STATS_G 256
#define MAX_GROUPS 512          // BNK/128

// ---------------- scratch (device globals; no allocation allowed) ----------
__device__ float g_inner[(size_t)Bb*Nn*Nn];   // [b][src q][dst p]
__device__ float g_buf1[(size_t)BNK*CO_MAIN];
__device__ float g_buf2[(size_t)BNK*CO_MAIN];
__device__ float g_descT_src[(size_t)BN_TOT*Cc];
__device__ float g_descT_dst[(size_t)BN_TOT*Cc];
__device__ float g_nbrT_src[(size_t)BN_TOT*Cc];   // [b][c][n]
__device__ float g_nbrT_dst[(size_t)BN_TOT*Cc];
__device__ float g_norm_src[BN_TOT], g_norm_dst[BN_TOT];
__device__ float g_n2_dst[BN_TOT];
__device__ float g_nbrnorm_src[BN_TOT], g_nbrnorm_dst[BN_TOT];
__device__ int   g_idx[BNK];
__device__ int   g_sidx[BNK];
__device__ float g_maxq[BN_TOT];
__device__ float g_maxp[BN_TOT];
__device__ float g_sims[(size_t)4*BNK];
__device__ float g_att[(size_t)BN_TOT*CO_MAIN];   // also reused as Pn
__device__ float g_h1[(size_t)BN_TOT*CO_MAIN];    // also reused as Ps
__device__ float g_h2[(size_t)BN_TOT*CO_MAIN];    // also reused as Pd
__device__ float g_psum[MAX_GROUPS*CO_MAIN];
__device__ float g_psq[MAX_GROUPS*CO_MAIN];
__device__ float g_scale[CO_MAIN], g_shift[CO_MAIN];
// packed layer-1 weight blocks
__device__ float g_W0s[CO_MAIN*Cc];
__device__ float g_W0d[CO_MAIN*Cc];
__device__ float g_W0r[CO_MAIN*16];
__device__ float g_W0nd[CO_NBR*Cc];
__device__ float g_W0ng[CO_NBR*4];

// ---------------- weight pack kernels --------------------------------------
__global__ void pack_kernel(const float* __restrict__ in, float* __restrict__ out,
                            int n, int kout, int stride, int off) {
    int i = blockIdx.x * blockDim.x + threadIdx.x;
    if (i >= n * kout) return;
    int r = i / kout, k = i % kout;
    out[i] = in[(size_t)r * stride + off + k];
}

__global__ void pack_w0r_kernel(const float* __restrict__ in) {
    int i = blockIdx.x * blockDim.x + threadIdx.x;
    if (i >= CO_MAIN * 16) return;
    int r = i >> 4, k = i & 15;
    int col = (k < 10) ? k : (k + 256);
    g_W0r[i] = in[(size_t)r * CH_MAIN + col];
}

// ---------------- transpose [B,C,N] -> [B,N,C] -----------------------------
__global__ void transpose_kernel(const float* __restrict__ in, float* __restrict__ out) {
    __shared__ float t[32][33];
    int b = blockIdx.z;
    int n0 = blockIdx.x * 32, c0 = blockIdx.y * 32;
    int x = threadIdx.x, y = threadIdx.y;
#pragma unroll
    for (int i = 0; i < 32; i += 8)
        t[y + i][x] = in[(size_t)b*Cc*Nn + (size_t)(c0 + y + i)*Nn + n0 + x];
    __syncthreads();
#pragma unroll
    for (int i = 0; i < 32; i += 8)
        out[(size_t)b*Nn*Cc + (size_t)(n0 + y + i)*Cc + c0 + x] = t[x][y + i];
}

// ---------------- per-point descriptor norms -------------------------------
__global__ void norms_kernel(const float* __restrict__ descT, float* __restrict__ nrm,
                             float* __restrict__ n2) {
    __shared__ float red[128];
    int bn = blockIdx.x; int c = threadIdx.x;
    float v = descT[(size_t)bn*Cc + c];
    red[c] = v * v; __syncthreads();
    for (int off = 64; off > 0; off >>= 1) {
        if (c < off) red[c] += red[c + off];
        __syncthreads();
    }
    if (c == 0) { float s = red[0]; if (n2) n2[bn] = s; nrm[bn] = sqrtf(s); }
}

// ---------------- fused BN+ReLU on a float4 of A ---------------------------
__device__ __forceinline__ float4 apply4(float4 a, int k) {
    float4 sc = *(const float4*)&g_scale[k];
    float4 sh = *(const float4*)&g_shift[k];
    a.x = fmaxf(fmaf(a.x, sc.x, sh.x), 0.f);
    a.y = fmaxf(fmaf(a.y, sc.y, sh.y), 0.f);
    a.z = fmaxf(fmaf(a.z, sc.z, sh.z), 0.f);
    a.w = fmaxf(fmaf(a.w, sc.w, sh.w), 0.f);
    return a;
}

// ---------------- NT gemm 128x128x8, 8x8/thread, double-buffered -----------
// C[m][n] = sum_k A[m][k] * W[n][k].  Kc multiple of 8.
// fuse!=0: A := relu(A*g_scale[k]+g_shift[k]) on load.
// stats!=0: write per-block column sum/sumsq partials to g_psum/g_psq[by][col].
__global__ void gemm_nt128_kernel(const float* __restrict__ A, const float* __restrict__ W,
                                  float* __restrict__ Cm, int M, int Nc, int Kc,
                                  int fuse, int stats) {
    __shared__ float As[2][8][128];
    __shared__ float Bs[2][8][128];
    __shared__ float Ss[16][128];
    __shared__ float Qs[16][128];
    int m0 = blockIdx.y * 128, n0 = blockIdx.x * 128;
    int tid = threadIdx.x;
    int lr = tid >> 1;
    int lk = (tid & 1) * 4;
    int ty = tid >> 4, tx = tid & 15;
    const float* Arow = A + (size_t)(m0 + lr) * Kc + lk;
    const float* Wrow = W + (size_t)(n0 + lr) * Kc + lk;
    float acc[8][8];
#pragma unroll
    for (int i = 0; i < 8; i++)
#pragma unroll
        for (int j = 0; j < 8; j++) acc[i][j] = 0.f;

    float4 av = *(const float4*)Arow;
    float4 bv = *(const float4*)Wrow;
    if (fuse) av = apply4(av, lk);
    As[0][lk+0][lr] = av.x; As[0][lk+1][lr] = av.y;
    As[0][lk+2][lr] = av.z; As[0][lk+3][lr] = av.w;
    Bs[0][lk+0][lr] = bv.x; Bs[0][lk+1][lr] = bv.y;
    Bs[0][lk+2][lr] = bv.z; Bs[0][lk+3][lr] = bv.w;
    __syncthreads();
    int nb = 0;
    for (int kt = 0; kt < Kc; kt += 8) {
        bool nxt = (kt + 8) < Kc;
        float4 a2, b2;
        if (nxt) {
            a2 = *(const float4*)(Arow + kt + 8);
            b2 = *(const float4*)(Wrow + kt + 8);
            if (fuse) a2 = apply4(a2, kt + 8 + lk);
        }
#pragma unroll
        for (int kkk = 0; kkk < 8; kkk++) {
            float a[8], b[8];
            *(float4*)&a[0] = *(const float4*)&As[nb][kkk][ty * 4];
            *(float4*)&a[4] = *(const float4*)&As[nb][kkk][64 + ty * 4];
            *(float4*)&b[0] = *(const float4*)&Bs[nb][kkk][tx * 4];
            *(float4*)&b[4] = *(const float4*)&Bs[nb][kkk][64 + tx * 4];
#pragma unroll
            for (int i = 0; i < 8; i++)
#pragma unroll
                for (int j = 0; j < 8; j++) acc[i][j] = fmaf(a[i], b[j], acc[i][j]);
        }
        if (nxt) {
            int nb2 = nb ^ 1;
            As[nb2][lk+0][lr] = a2.x; As[nb2][lk+1][lr] = a2.y;
            As[nb2][lk+2][lr] = a2.z; As[nb2][lk+3][lr] = a2.w;
            Bs[nb2][lk+0][lr] = b2.x; Bs[nb2][lk+1][lr] = b2.y;
            Bs[nb2][lk+2][lr] = b2.z; Bs[nb2][lk+3][lr] = b2.w;
            nb = nb2;
        }
        __syncthreads();
    }
#pragma unroll
    for (int i = 0; i < 8; i++) {
        int row = m0 + ((i < 4) ? (ty * 4 + i) : (64 + ty * 4 + i - 4));
        *(float4*)&Cm[(size_t)row * Nc + n0 + tx * 4] =
            make_float4(acc[i][0], acc[i][1], acc[i][2], acc[i][3]);
        *(float4*)&Cm[(size_t)row * Nc + n0 + 64 + tx * 4] =
            make_float4(acc[i][4], acc[i][5], acc[i][6], acc[i][7]);
    }
    if (stats) {
        // per-thread column partials over its 8 rows
#pragma unroll
        for (int j = 0; j < 8; j++) {
            float s = 0.f, q = 0.f;
#pragma unroll
            for (int i = 0; i < 8; i++) { s += acc[i][j]; q += acc[i][j]*acc[i][j]; }
            int lc = (j < 4) ? (tx * 4 + j) : (64 + tx * 4 + j - 4);
            Ss[ty][lc] = s; Qs[ty][lc] = q;
        }
        __syncthreads();
        if (tid < 128) {
            float s = 0.f, q = 0.f;
#pragma unroll
            for (int r = 0; r < 16; r++) { s += Ss[r][tid]; q += Qs[r][tid]; }
            g_psum[(size_t)blockIdx.y * Nc + n0 + tid] = s;
            g_psq[(size_t)blockIdx.y * Nc + n0 + tid]  = q;
        }
    }
}

// ---------------- TN gemm 128x128x8 (batched over Bb) ----------------------
__global__ void gemm_tn128_kernel(const float* __restrict__ A, const float* __restrict__ Bm,
                                  float* __restrict__ Cm, int Kc) {
    __shared__ float As[2][8][128];
    __shared__ float Bs[2][8][128];
    int b = blockIdx.z;
    const float* Ab = A + (size_t)b * Kc * Nn;
    const float* Bp = Bm + (size_t)b * Kc * Nn;
    float* Cb = Cm + (size_t)b * Nn * Nn;
    int m0 = blockIdx.y * 128, n0 = blockIdx.x * 128;
    int tid = threadIdx.x;
    int lk2 = tid >> 5;
    int lm = (tid & 31) * 4;
    int ty = tid >> 4, tx = tid & 15;
    float acc[8][8];
#pragma unroll
    for (int i = 0; i < 8; i++)
#pragma unroll
        for (int j = 0; j < 8; j++) acc[i][j] = 0.f;

    *(float4*)&As[0][lk2][lm] = *(const float4*)&Ab[(size_t)lk2 * Nn + m0 + lm];
    *(float4*)&Bs[0][lk2][lm] = *(const float4*)&Bp[(size_t)lk2 * Nn + n0 + lm];
    __syncthreads();
    int nb = 0;
    for (int kt = 0; kt < Kc; kt += 8) {
        bool nxt = (kt + 8) < Kc;
        float4 a2, b2;
        if (nxt) {
            a2 = *(const float4*)&Ab[(size_t)(kt + 8 + lk2) * Nn + m0 + lm];
            b2 = *(const float4*)&Bp[(size_t)(kt + 8 + lk2) * Nn + n0 + lm];
        }
#pragma unroll
        for (int kkk = 0; kkk < 8; kkk++) {
            float a[8], b[8];
            *(float4*)&a[0] = *(const float4*)&As[nb][kkk][ty * 4];
            *(float4*)&a[4] = *(const float4*)&As[nb][kkk][64 + ty * 4];
            *(float4*)&b[0] = *(const float4*)&Bs[nb][kkk][tx * 4];
            *(float4*)&b[4] = *(const float4*)&Bs[nb][kkk][64 + tx * 4];
#pragma unroll
            for (int i = 0; i < 8; i++)
#pragma unroll
                for (int j = 0; j < 8; j++) acc[i][j] = fmaf(a[i], b[j], acc[i][j]);
        }
        if (nxt) {
            int nb2 = nb ^ 1;
            *(float4*)&As[nb2][lk2][lm] = a2;
            *(float4*)&Bs[nb2][lk2][lm] = b2;
            nb = nb2;
        }
        __syncthreads();
    }
#pragma unroll
    for (int i = 0; i < 8; i++) {
        int row = m0 + ((i < 4) ? (ty * 4 + i) : (64 + ty * 4 + i - 4));
        *(float4*)&Cb[(size_t)row * Nn + n0 + tx * 4] =
            make_float4(acc[i][0], acc[i][1], acc[i][2], acc[i][3]);
        *(float4*)&Cb[(size_t)row * Nn + n0 + 64 + tx * 4] =
            make_float4(acc[i][4], acc[i][5], acc[i][6], acc[i][7]);
    }
}

// ---------------- layer-1 combine kernels ----------------------------------
__global__ void main_l1_combine_kernel(const float* __restrict__ sxyz,
                                       const float* __restrict__ dxyz,
                                       const float* __restrict__ sw,
                                       const float* __restrict__ dw,
                                       const float* __restrict__ Ps,
                                       const float* __restrict__ Pd,
                                       float* __restrict__ Y) {
    __shared__ float rest[16];
    int t = blockIdx.x;
    int bn = t >> 4; int b = bn >> 11;
    int i = g_idx[t]; int gi = b*Nn + i;
    int o = threadIdx.x;
    if (o == 0) {
        float sx = sxyz[bn*3+0], sy = sxyz[bn*3+1], sz = sxyz[bn*3+2];
        float kx = dxyz[gi*3+0], ky = dxyz[gi*3+1], kz = dxyz[gi*3+2];
        float dx = kx - sx, dy = ky - sy, dz = kz - sz;
        rest[0] = dx; rest[1] = dy; rest[2] = dz;
        rest[3] = sqrtf(dx*dx + dy*dy + dz*dz);
        rest[4] = sx; rest[5] = sy; rest[6] = sz;
        rest[7] = kx; rest[8] = ky; rest[9] = kz;
        rest[10] = sw[bn]; rest[11] = dw[gi];
        rest[12] = g_sims[0*(size_t)BNK + t];
        rest[13] = g_sims[1*(size_t)BNK + t];
        rest[14] = g_sims[2*(size_t)BNK + t];
        rest[15] = g_sims[3*(size_t)BNK + t];
    }
    __syncthreads();
    float acc = Ps[(size_t)bn*CO_MAIN + o] + Pd[(size_t)gi*CO_MAIN + o];
    const float4* w = (const float4*)&g_W0r[o * 16];
#pragma unroll
    for (int r = 0; r < 4; r++) {
        float4 wv = w[r];
        acc += wv.x*rest[r*4+0] + wv.y*rest[r*4+1] + wv.z*rest[r*4+2] + wv.w*rest[r*4+3];
    }
    Y[(size_t)t*CO_MAIN + o] = acc;
}

__global__ void nbr_l1_combine_kernel(const float* __restrict__ xyz,
                                      const float* __restrict__ Pn,
                                      float* __restrict__ Y) {
    __shared__ float rest[4];
    int t = blockIdx.x;
    int bn = t >> 4; int b = bn >> 11;
    int i = g_sidx[t]; int gi = b*Nn + i;
    int o = threadIdx.x;
    if (o == 0) {
        float dx = xyz[gi*3+0] - xyz[bn*3+0];
        float dy = xyz[gi*3+1] - xyz[bn*3+1];
        float dz = xyz[gi*3+2] - xyz[bn*3+2];
        rest[0] = dx; rest[1] = dy; rest[2] = dz;
        rest[3] = sqrtf(dx*dx + dy*dy + dz*dz);
    }
    __syncthreads();
    float4 wv = *(const float4*)&g_W0ng[o * 4];
    float acc = Pn[(size_t)gi*CO_NBR + o]
              + wv.x*rest[0] + wv.y*rest[1] + wv.z*rest[2] + wv.w*rest[3];
    Y[(size_t)t*CO_NBR + o] = acc;
}

// ---------------- BatchNorm stats ------------------------------------------
__global__ void bn_stats1_kernel(const float* __restrict__ Y, int M, int Cout) {
    int c = threadIdx.x;
    float s = 0.f, s2 = 0.f;
    for (int r = blockIdx.x; r < M; r += STATS_G) {
        float v = Y[(size_t)r*Cout + c];
        s += v; s2 += v * v;
    }
    g_psum[blockIdx.x*Cout + c] = s;
    g_psq[blockIdx.x*Cout + c]  = s2;
}

__global__ void bn_stats2_kernel(int M, int Cout, int ngroups,
                                 const float* __restrict__ gamma,
                                 const float* __restrict__ beta) {
    int c = threadIdx.x;
    float s = 0.f, s2 = 0.f;
    for (int g = 0; g < ngroups; g++) { s += g_psum[(size_t)g*Cout + c]; s2 += g_psq[(size_t)g*Cout + c]; }
    float inv = 1.f / (float)M;
    float mu = s * inv;
    float var = fmaxf(s2 * inv - mu * mu, 0.f);
    float sc = gamma[c] * rsqrtf(var + BNEPSf);
    g_scale[c] = sc;
    g_shift[c] = beta[c] - mu * sc;
}

__global__ void bn_apply_relu_kernel(float* __restrict__ Y, int total, int cmask) {
    int i = blockIdx.x * blockDim.x + threadIdx.x;
    if (i >= total) return;
    int c = i & cmask;
    Y[i] = fmaxf(Y[i] * g_scale[c] + g_shift[c], 0.f);
}

// ---------------- argmin helper (warp shuffle) -----------------------------
__device__ __forceinline__ void argmin_round(const float* key, int n, int tid,
                                             float* wrv, int* wri,
                                             int* out_slot, float* keymut) {
    float bv = FLT_MAX; int bi = n;
    for (int i = tid; i < n; i += 256) {
        float v = key[i];
        if (v < bv) { bv = v; bi = i; }
    }
#pragma unroll
    for (int o = 16; o > 0; o >>= 1) {
        float v2 = __shfl_xor_sync(0xffffffffu, bv, o);
        int   i2 = __shfl_xor_sync(0xffffffffu, bi, o);
        if (v2 < bv || (v2 == bv && i2 < bi)) { bv = v2; bi = i2; }
    }
    int lane = tid & 31, wid = tid >> 5;
    if (lane == 0) { wrv[wid] = bv; wri[wid] = bi; }
    __syncthreads();
    if (tid == 0) {
        float mv = wrv[0]; int mi = wri[0];
#pragma unroll
        for (int r = 1; r < 8; r++) {
            if (wrv[r] < mv || (wrv[r] == mv && wri[r] < mi)) { mv = wrv[r]; mi = wri[r]; }
        }
        *out_slot = mi;
        keymut[mi] = FLT_MAX;
    }
    __syncthreads();
}

// ---------------- KNN (descriptor space): row-coalesced --------------------
__global__ void knn_desc_kernel() {
    __shared__ float key[Nn];
    __shared__ float wrv[8]; __shared__ int wri[8];
    __shared__ int slot;
    int bj = blockIdx.x;
    const float* row = g_inner + (size_t)bj*Nn;
    int b = bj >> 11;
    int tid = threadIdx.x;
    for (int i = tid; i < Nn; i += 256)
        key[i] = g_n2_dst[b*Nn + i] - 2.f * row[i];
    __syncthreads();
    for (int s = 0; s < Kk; s++) {
        argmin_round(key, Nn, tid, wrv, wri, &slot, key);
        if (tid == 0) g_idx[bj*Kk + s] = slot;
    }
}

// ---------------- KNN (spatial, self) --------------------------------------
__global__ void knn_spatial_kernel(const float* __restrict__ xyz, int* __restrict__ oidx) {
    __shared__ float key[Nn];
    __shared__ float wrv[8]; __shared__ int wri[8];
    __shared__ int slot;
    int bj = blockIdx.x; int b = bj >> 11;
    int tid = threadIdx.x;
    float qx = xyz[(size_t)bj*3 + 0], qy = xyz[(size_t)bj*3 + 1], qz = xyz[(size_t)bj*3 + 2];
    const float* xb = xyz + (size_t)b*Nn*3;
    for (int i = tid; i < Nn; i += 256) {
        float dx = xb[i*3 + 0] - qx, dy = xb[i*3 + 1] - qy, dz = xb[i*3 + 2] - qz;
        key[i] = dx*dx + dy*dy + dz*dz;
    }
    __syncthreads();
    for (int s = 0; s < Kk; s++) {
        argmin_round(key, Nn, tid, wrv, wri, &slot, key);
        if (tid == 0) oidx[bj*Kk + s] = slot;
    }
}

// ---------------- cosine maxima over inner[b][q][p] ------------------------
__global__ void rowmax_kernel(const float* __restrict__ nq, const float* __restrict__ np) {
    __shared__ float red[256];
    int bq = blockIdx.x; int b = bq >> 11;
    const float* row = g_inner + (size_t)bq*Nn;
    float nqv = nq[bq];
    const float* npb = np + b*Nn;
    float m = -FLT_MAX;
    for (int p = threadIdx.x; p < Nn; p += 256)
        m = fmaxf(m, row[p] / (nqv * npb[p] + EPSf));
    red[threadIdx.x] = m; __syncthreads();
    for (int off = 128; off > 0; off >>= 1) {
        if (threadIdx.x < off) red[threadIdx.x] = fmaxf(red[threadIdx.x], red[threadIdx.x + off]);
        __syncthreads();
    }
    if (threadIdx.x == 0) g_maxq[bq] = red[0];
}

__global__ void colmax_kernel(const float* __restrict__ nq, const float* __restrict__ np) {
    __shared__ float sm[8][32];
    int b = blockIdx.y;
    int p = blockIdx.x * 32 + threadIdx.x;
    float npv = np[b*Nn + p];
    const float* colb = g_inner + (size_t)b*Nn*Nn + p;
    const float* nqb = nq + b*Nn;
    float m = -FLT_MAX;
    for (int q = threadIdx.y; q < Nn; q += 8)
        m = fmaxf(m, colb[(size_t)q*Nn] / (nqb[q] * npv + EPSf));
    sm[threadIdx.y][threadIdx.x] = m; __syncthreads();
    if (threadIdx.y == 0) {
#pragma unroll
        for (int r = 1; r < 8; r++) m = fmaxf(m, sm[r][threadIdx.x]);
        g_maxp[b*Nn + p] = m;
    }
}

__global__ void gather_sims_kernel(const float* __restrict__ nd, const float* __restrict__ ns,
                                   float* __restrict__ s1, float* __restrict__ s2) {
    int t = blockIdx.x * blockDim.x + threadIdx.x;
    if (t >= BNK) return;
    int bn = t >> 4; int b = bn >> 11;
    int i = g_idx[t];
    float innv = g_inner[(size_t)bn*Nn + i];
    float cosv = innv / (nd[b*Nn + i] * ns[bn] + EPSf);
    s1[t] = cosv / (g_maxq[bn] + EPSf);
    s2[t] = cosv / (g_maxp[b*Nn + i] + EPSf);
}

// ---------------- neighbor-branch finalize (reads activated buf1) ----------
__global__ void nbr_finalize_kernel(const float* __restrict__ descT, float* __restrict__ nbrT,
                                    float* __restrict__ nnorm) {
    __shared__ float red[128]; __shared__ float wk[Kk];
    int bn = blockIdx.x; int b = bn >> 11; int n = bn & (Nn - 1);
    int c = threadIdx.x;
    for (int k = 0; k < Kk; k++) {
        red[c] = g_buf1[((size_t)bn*Kk + k)*CO_NBR + c];
        __syncthreads();
        for (int off = 64; off > 0; off >>= 1) {
            if (c < off) red[c] = fmaxf(red[c], red[c + off]);
            __syncthreads();
        }
        if (c == 0) wk[k] = red[0];
        __syncthreads();
    }
    if (c == 0) {
        float mx = -FLT_MAX;
        for (int k = 0; k < Kk; k++) mx = fmaxf(mx, wk[k]);
        float s = 0.f;
        for (int k = 0; k < Kk; k++) { wk[k] = expf(wk[k] - mx); s += wk[k]; }
        float is = 1.f / s;
        for (int k = 0; k < Kk; k++) wk[k] *= is;
    }
    __syncthreads();
    float acc = 0.f;
    for (int k = 0; k < Kk; k++) {
        int i = g_sidx[bn*Kk + k];
        acc += wk[k] * descT[(size_t)(b*Nn + i)*Cc + c];
    }
    nbrT[(size_t)b*Cc*Nn + (size_t)c*Nn + n] = acc;
    red[c] = acc * acc; __syncthreads();
    for (int off = 64; off > 0; off >>= 1) {
        if (c < off) red[c] += red[c + off];
        __syncthreads();
    }
    if (c == 0) nnorm[bn] = sqrtf(red[0]);
}

// ---------------- attention pooling (reads activated buf1) -----------------
__global__ void att_finalize_kernel(const float* __restrict__ dxyz, float* __restrict__ out_corres) {
    __shared__ float red[256]; __shared__ float wk[Kk];
    int bn = blockIdx.x; int b = bn >> 11;
    int c = threadIdx.x;
    for (int k = 0; k < Kk; k++) {
        red[c] = g_buf1[((size_t)bn*Kk + k)*CO_MAIN + c];
        __syncthreads();
        for (int off = 128; off > 0; off >>= 1) {
            if (c < off) red[c] = fmaxf(red[c], red[c + off]);
            __syncthreads();
        }
        if (c == 0) wk[k] = red[0];
        __syncthreads();
    }
    if (c == 0) {
        float mx = -FLT_MAX;
        for (int k = 0; k < Kk; k++) mx = fmaxf(mx, wk[k]);
        float s = 0.f;
        for (int k = 0; k < Kk; k++) { wk[k] = expf(wk[k] - mx); s += wk[k]; }
        float is = 1.f / s;
        for (int k = 0; k < Kk; k++) wk[k] *= is;
    }
    __syncthreads();
    float acc = 0.f;
    for (int k = 0; k < Kk; k++)
        acc += wk[k] * g_buf1[((size_t)bn*Kk + k)*CO_MAIN + c];
    g_att[(size_t)bn*CO_MAIN + c] = acc;
    if (c < 3) {
        float s = 0.f;
        for (int k = 0; k < Kk; k++) {
            int i = g_idx[bn*Kk + k];
            s += wk[k] * dxyz[(b*Nn + i)*3 + c];
        }
        out_corres[bn*3 + c] = s;
    }
}

// ---------------- final sigmoid head ---------------------------------------
__global__ void mlp3_kernel(const float* __restrict__ W, const float* __restrict__ bias,
                            float* __restrict__ out) {
    __shared__ float red[256];
    int bn = blockIdx.x; int c = threadIdx.x;
    red[c] = g_h2[(size_t)bn*CO_MAIN + c] * W[c];
    __syncthreads();
    for (int off = 128; off > 0; off >>= 1) {
        if (c < off) red[c] += red[c + off];
        __syncthreads();
    }
    if (c == 0) {
        float z = red[0] + bias[0];
        out[bn] = 1.f / (1.f + expf(-z));
    }
}

// ---------------- host-side helpers ----------------------------------------
static void bn_stats_full(const float* Y, int M, int Cout, const float* gamma, const float* beta) {
    bn_stats1_kernel<<<STATS_G, Cout>>>(Y, M, Cout);
    bn_stats2_kernel<<<1, Cout>>>(M, Cout, STATS_G, gamma, beta);
}

static void bn_apply(float* Y, int M, int Cout) {
    int total = M * Cout;
    bn_apply_relu_kernel<<<(total + 255) / 256, 256>>>(Y, total, Cout - 1);
}

// gemm with fused BN-on-A-read + epilogue partial stats, then stats fold
static void conv_stats(const float* X, const float* W, float* Y, int M, int Cout, int Cin,
                       int fuse, const float* gamma, const float* beta) {
    gemm_nt128_kernel<<<dim3(Cout / 128, M / 128), 256>>>(X, W, Y, M, Cout, Cin, fuse, 1);
    bn_stats2_kernel<<<1, Cout>>>(M, Cout, M / 128, gamma, beta);
}

extern "C" void kernel_launch(void* const* d_in, const int* in_sizes, int n_in,
                              void* d_out, int out_size) {
    const float* src_xyz  = (const float*)d_in[0];
    const float* src_desc = (const float*)d_in[1];
    const float* dst_xyz  = (const float*)d_in[2];
    const float* dst_desc = (const float*)d_in[3];
    const float* src_w    = (const float*)d_in[4];
    const float* dst_w    = (const float*)d_in[5];
    const float* c1_W0 = (const float*)d_in[6];
    const float* c1_W  = (const float*)d_in[7];
    const float* c1_g  = (const float*)d_in[8];
    const float* c1_b  = (const float*)d_in[9];
    const float* c2_W0 = (const float*)d_in[10];
    const float* c2_W  = (const float*)d_in[11];
    const float* c2_g  = (const float*)d_in[12];
    const float* c2_b  = (const float*)d_in[13];
    const float* m1_W  = (const float*)d_in[14];
    // d_in[15] m1_bias: cancels exactly under train-mode BN
    const float* m1_g  = (const float*)d_in[16];
    const float* m1_b  = (const float*)d_in[17];
    const float* m2_W  = (const float*)d_in[18];
    // d_in[19] m2_bias: cancels under BN
    const float* m2_g  = (const float*)d_in[20];
    const float* m2_b  = (const float*)d_in[21];
    const float* m3_W  = (const float*)d_in[22];
    const float* m3_bias = (const float*)d_in[23];
    float* outp = (float*)d_out;

    float *inner, *buf1, *buf2, *dTs, *dTd, *nTs, *nTd;
    float *nsrc, *ndst, *n2d, *nnsrc, *nndst, *sims, *att, *h1, *h2;
    float *W0s, *W0d, *W0nd, *W0ng;
    int *sidxp;
    cudaGetSymbolAddress((void**)&inner, g_inner);
    cudaGetSymbolAddress((void**)&buf1,  g_buf1);
    cudaGetSymbolAddress((void**)&buf2,  g_buf2);
    cudaGetSymbolAddress((void**)&dTs,   g_descT_src);
    cudaGetSymbolAddress((void**)&dTd,   g_descT_dst);
    cudaGetSymbolAddress((void**)&nTs,   g_nbrT_src);
    cudaGetSymbolAddress((void**)&nTd,   g_nbrT_dst);
    cudaGetSymbolAddress((void**)&nsrc,  g_norm_src);
    cudaGetSymbolAddress((void**)&ndst,  g_norm_dst);
    cudaGetSymbolAddress((void**)&n2d,   g_n2_dst);
    cudaGetSymbolAddress((void**)&nnsrc, g_nbrnorm_src);
    cudaGetSymbolAddress((void**)&nndst, g_nbrnorm_dst);
    cudaGetSymbolAddress((void**)&sims,  g_sims);
    cudaGetSymbolAddress((void**)&att,   g_att);
    cudaGetSymbolAddress((void**)&h1,    g_h1);
    cudaGetSymbolAddress((void**)&h2,    g_h2);
    cudaGetSymbolAddress((void**)&W0s,   g_W0s);
    cudaGetSymbolAddress((void**)&W0d,   g_W0d);
    cudaGetSymbolAddress((void**)&W0nd,  g_W0nd);
    cudaGetSymbolAddress((void**)&W0ng,  g_W0ng);
    cudaGetSymbolAddress((void**)&sidxp, g_sidx);

    // Stage 0: transpose descriptors, norms, pack layer-1 weight blocks
    transpose_kernel<<<dim3(Nn/32, Cc/32, Bb), dim3(32, 8)>>>(src_desc, dTs);
    transpose_kernel<<<dim3(Nn/32, Cc/32, Bb), dim3(32, 8)>>>(dst_desc, dTd);
    norms_kernel<<<BN_TOT, 128>>>(dTs, nsrc, (float*)0);
    norms_kernel<<<BN_TOT, 128>>>(dTd, ndst, n2d);
    pack_kernel<<<(CO_MAIN*Cc + 255)/256, 256>>>(c1_W0, W0s, CO_MAIN, Cc, CH_MAIN, 10);
    pack_kernel<<<(CO_MAIN*Cc + 255)/256, 256>>>(c1_W0, W0d, CO_MAIN, Cc, CH_MAIN, 138);
    pack_w0r_kernel<<<(CO_MAIN*16 + 255)/256, 256>>>(c1_W0);
    pack_kernel<<<(CO_NBR*Cc + 255)/256, 256>>>(c2_W0, W0nd, CO_NBR, Cc, CH_NBR, 0);
    pack_kernel<<<(CO_NBR*4 + 255)/256, 256>>>(c2_W0, W0ng, CO_NBR, 4, CH_NBR, 128);

    // Stage 1: inner[b][src][dst], knn (row-coalesced), sims 0/1
    gemm_tn128_kernel<<<dim3(Nn/128, Nn/128, Bb), 256>>>(src_desc, dst_desc, inner, Cc);
    knn_desc_kernel<<<BN_TOT, 256>>>();
    rowmax_kernel<<<BN_TOT, 256>>>(nsrc, ndst);
    colmax_kernel<<<dim3(Nn/32, Bb), dim3(32, 8)>>>(nsrc, ndst);
    gather_sims_kernel<<<BNK/256, 256>>>(ndst, nsrc, sims + 0*(size_t)BNK, sims + 1*(size_t)BNK);

    // Stage 2a: neighbor branch, src cloud
    knn_spatial_kernel<<<BN_TOT, 256>>>(src_xyz, sidxp);
    gemm_nt128_kernel<<<dim3(1, BN_TOT/128), 256>>>(dTs, W0nd, att /*Pn*/, BN_TOT, CO_NBR, Cc, 0, 0);
    nbr_l1_combine_kernel<<<BNK, CO_NBR>>>(src_xyz, att, buf1);
    bn_stats_full(buf1, BNK, CO_NBR, c2_g + 0*Cc, c2_b + 0*Cc);
    conv_stats(buf1, c2_W + 0*Cc*Cc, buf2, BNK, CO_NBR, Cc, 1, c2_g + 1*Cc, c2_b + 1*Cc);
    conv_stats(buf2, c2_W + 1*Cc*Cc, buf1, BNK, CO_NBR, Cc, 1, c2_g + 2*Cc, c2_b + 2*Cc);
    bn_apply(buf1, BNK, CO_NBR);
    nbr_finalize_kernel<<<BN_TOT, 128>>>(dTs, nTs, nnsrc);

    // Stage 2b: neighbor branch, dst cloud
    knn_spatial_kernel<<<BN_TOT, 256>>>(dst_xyz, sidxp);
    gemm_nt128_kernel<<<dim3(1, BN_TOT/128), 256>>>(dTd, W0nd, att /*Pn*/, BN_TOT, CO_NBR, Cc, 0, 0);
    nbr_l1_combine_kernel<<<BNK, CO_NBR>>>(dst_xyz, att, buf1);
    bn_stats_full(buf1, BNK, CO_NBR, c2_g + 0*Cc, c2_b + 0*Cc);
    conv_stats(buf1, c2_W + 0*Cc*Cc, buf2, BNK, CO_NBR, Cc, 1, c2_g + 1*Cc, c2_b + 1*Cc);
    conv_stats(buf2, c2_W + 1*Cc*Cc, buf1, BNK, CO_NBR, Cc, 1, c2_g + 2*Cc, c2_b + 2*Cc);
    bn_apply(buf1, BNK, CO_NBR);
    nbr_finalize_kernel<<<BN_TOT, 128>>>(dTd, nTd, nndst);

    // Stage 3: neighbor cosine sims 2/3
    gemm_tn128_kernel<<<dim3(Nn/128, Nn/128, Bb), 256>>>(nTs, nTd, inner, Cc);
    rowmax_kernel<<<BN_TOT, 256>>>(nnsrc, nndst);
    colmax_kernel<<<dim3(Nn/32, Bb), dim3(32, 8)>>>(nnsrc, nndst);
    gather_sims_kernel<<<BNK/256, 256>>>(nndst, nnsrc, sims + 2*(size_t)BNK, sims + 3*(size_t)BNK);

    // Stage 4: main branch
    gemm_nt128_kernel<<<dim3(CO_MAIN/128, BN_TOT/128), 256>>>(dTs, W0s, h1 /*Ps*/, BN_TOT, CO_MAIN, Cc, 0, 0);
    gemm_nt128_kernel<<<dim3(CO_MAIN/128, BN_TOT/128), 256>>>(dTd, W0d, h2 /*Pd*/, BN_TOT, CO_MAIN, Cc, 0, 0);
    main_l1_combine_kernel<<<BNK, CO_MAIN>>>(src_xyz, dst_xyz, src_w, dst_w, h1, h2, buf1);
    bn_stats_full(buf1, BNK, CO_MAIN, c1_g + 0*CO_MAIN, c1_b + 0*CO_MAIN);
    conv_stats(buf1, c1_W + 0*CO_MAIN*CO_MAIN, buf2, BNK, CO_MAIN, CO_MAIN, 1,
               c1_g + 1*CO_MAIN, c1_b + 1*CO_MAIN);
    conv_stats(buf2, c1_W + 1*CO_MAIN*CO_MAIN, buf1, BNK, CO_MAIN, CO_MAIN, 1,
               c1_g + 2*CO_MAIN, c1_b + 2*CO_MAIN);
    bn_apply(buf1, BNK, CO_MAIN);
    att_finalize_kernel<<<BN_TOT, 256>>>(dst_xyz, outp);

    // Stage 5: MLP head (m1/m2 biases cancel in BN)
    gemm_nt128_kernel<<<dim3(CO_MAIN/128, BN_TOT/128), 256>>>(att, m1_W, h1, BN_TOT, CO_MAIN, CO_MAIN, 0, 1);
    bn_stats2_kernel<<<1, CO_MAIN>>>(BN_TOT, CO_MAIN, BN_TOT/128, m1_g, m1_b);
    conv_stats(h1, m2_W, h2, BN_TOT, CO_MAIN, CO_MAIN, 1, m2_g, m2_b);
    bn_apply(h2, BN_TOT, CO_MAIN);
    mlp3_kernel<<<BN_TOT, 256>>>(m3_W, m3_bias, outp + (size_t)BN_TOT*3);
}